// round 1
// baseline (speedup 1.0000x reference)
#include <cuda_runtime.h>
#include <math.h>

// ---------------------------------------------------------------------------
// Scratch buffers (device globals -- no allocation inside kernel_launch)
// Max activation: conv0 out = 64*8*128*96 = 6,291,456 floats
// Second buffer:  conv1 out = 64*16*64*48 = 3,145,728 floats
// ---------------------------------------------------------------------------
#define MAX_A 6400000
#define MAX_B 3300000
__device__ float g_bufA[MAX_A];
__device__ float g_bufB[MAX_B];

// ---------------------------------------------------------------------------
// Direct convolution, thread per output element. pad = 1 always.
// ---------------------------------------------------------------------------
template<int K, int S, bool RELU>
__global__ void conv_kernel(const float* __restrict__ in,
                            const float* __restrict__ w,
                            const float* __restrict__ bias,
                            float* __restrict__ out,
                            int B, int Cin, int Hin, int Win,
                            int Cout, int Hout, int Wout)
{
    int idx = blockIdx.x * blockDim.x + threadIdx.x;
    int total = B * Cout * Hout * Wout;
    if (idx >= total) return;

    int wo = idx % Wout;
    int t  = idx / Wout;
    int ho = t % Hout; t /= Hout;
    int co = t % Cout;
    int b  = t / Cout;

    int hbase = ho * S - 1;   // pad = 1
    int wbase = wo * S - 1;
    int kh0 = max(0, -hbase);
    int kh1 = min(K, Hin - hbase);
    int kw0 = max(0, -wbase);
    int kw1 = min(K, Win - wbase);

    const float* inb = in + (size_t)b * Cin * Hin * Win;
    const float* wc  = w  + (size_t)co * Cin * K * K;

    float acc = bias[co];
    for (int ci = 0; ci < Cin; ci++) {
        const float* inp = inb + (size_t)ci * Hin * Win;
        const float* wp  = wc + ci * K * K;
        for (int kh = kh0; kh < kh1; kh++) {
            const float* row = inp + (size_t)(hbase + kh) * Win + wbase;
            const float* wr  = wp + kh * K;
            #pragma unroll
            for (int kw = 0; kw < K; kw++) {
                if (kw >= kw0 && kw < kw1)
                    acc = fmaf(__ldg(row + kw), __ldg(wr + kw), acc);
            }
        }
    }
    if (RELU) acc = fmaxf(acc, 0.0f);
    out[idx] = acc;
}

// ---------------------------------------------------------------------------
// Instance norm (in-place), one block per (b,c) plane. Optional trailing ReLU.
// ---------------------------------------------------------------------------
template<bool RELU>
__global__ void inorm_kernel(float* __restrict__ data, int HW)
{
    float* p = data + (size_t)blockIdx.x * HW;
    float s = 0.f, ss = 0.f;
    for (int i = threadIdx.x; i < HW; i += blockDim.x) {
        float v = p[i];
        s  += v;
        ss += v * v;
    }
    __shared__ float sh_s[256];
    __shared__ float sh_ss[256];
    sh_s[threadIdx.x]  = s;
    sh_ss[threadIdx.x] = ss;
    __syncthreads();
    for (int off = blockDim.x >> 1; off > 0; off >>= 1) {
        if (threadIdx.x < off) {
            sh_s[threadIdx.x]  += sh_s[threadIdx.x + off];
            sh_ss[threadIdx.x] += sh_ss[threadIdx.x + off];
        }
        __syncthreads();
    }
    float invN = 1.0f / (float)HW;
    float m    = sh_s[0] * invN;
    float var  = sh_ss[0] * invN - m * m;
    float r    = rsqrtf(var + 1e-5f);
    for (int i = threadIdx.x; i < HW; i += blockDim.x) {
        float v = (p[i] - m) * r;
        if (RELU) v = fmaxf(v, 0.0f);
        p[i] = v;
    }
}

// ---------------------------------------------------------------------------
// Maxpool 2x2 stride 2 VALID on (64,256,4,3) -> flatten to (64,512)
// out[b, c*2+i] = max of in[b,c,2i..2i+1, 0..1]   (col 2 dropped)
// ---------------------------------------------------------------------------
__global__ void maxpool_kernel(const float* __restrict__ in, float* __restrict__ out)
{
    int idx = blockIdx.x * blockDim.x + threadIdx.x;
    if (idx >= 64 * 256 * 2) return;
    int i = idx % 2;
    int c = (idx / 2) % 256;
    int b = idx / 512;
    const float* p = in + (((size_t)b * 256 + c) * 4 + 2 * i) * 3;
    float v = fmaxf(fmaxf(p[0], p[1]), fmaxf(p[3], p[4]));
    out[(size_t)b * 512 + c * 2 + i] = v;
}

// ---------------------------------------------------------------------------
// FC1: (64,512) @ (128,512)^T + b, ReLU. One block per batch, thread per out.
// ---------------------------------------------------------------------------
__global__ void fc1_kernel(const float* __restrict__ in,
                           const float* __restrict__ w,
                           const float* __restrict__ bias,
                           float* __restrict__ out)
{
    int b = blockIdx.x;
    int j = threadIdx.x;           // 128 threads
    const float* x  = in + (size_t)b * 512;
    const float* wr = w  + (size_t)j * 512;
    float acc = bias[j];
    #pragma unroll 8
    for (int k = 0; k < 512; k++)
        acc = fmaf(x[k], __ldg(wr + k), acc);
    out[(size_t)b * 128 + j] = fmaxf(acc, 0.0f);
}

// ---------------------------------------------------------------------------
// FC2: (64,128) @ (50,128)^T + b, tanh. Writes coor directly into d_out.
// ---------------------------------------------------------------------------
__global__ void fc2_kernel(const float* __restrict__ in,
                           const float* __restrict__ w,
                           const float* __restrict__ bias,
                           float* __restrict__ out)
{
    int b = blockIdx.x;
    int j = threadIdx.x;           // 64 threads, guard at 50
    if (j >= 50) return;
    const float* x  = in + (size_t)b * 128;
    const float* wr = w  + (size_t)j * 128;
    float acc = bias[j];
    #pragma unroll 8
    for (int k = 0; k < 128; k++)
        acc = fmaf(x[k], __ldg(wr + k), acc);
    out[(size_t)b * 50 + j] = tanhf(acc);
}

// ---------------------------------------------------------------------------
// Loss kernel. Single block, 64 threads (thread = batch).
// pts = d_out[0..3199] holds coor (64,25,2). Scalars at d_out[3200..3205]:
//   rx, ry, cx, cy, rg, cg
// ---------------------------------------------------------------------------
__global__ void loss_kernel(float* __restrict__ out)
{
    const float* pts = out;
    int b = threadIdx.x;

    // grid[b][i][j][comp] = pts[b*50 + (i*5+j)*2 + comp]
    const float* g = pts + (size_t)b * 50;
    #define G(i, j, comp) g[((i) * 5 + (j)) * 2 + (comp)]

    float rx = 0.f, ry = 0.f, cx = 0.f, cy = 0.f;
    for (int i = 0; i < 5; i++) {
        for (int s = 0; s < 3; s++) {
            #pragma unroll
            for (int comp = 0; comp < 2; comp++) {
                // row terms: fixed row i, varying column
                float a0 = G(i, s, comp), a1 = G(i, s + 1, comp), a2 = G(i, s + 2, comp);
                float d0 = (a1 - a0) * (a1 - a0);
                float d1 = (a2 - a1) * (a2 - a1);
                float rv = fmaxf(0.08f, fabsf(d1 - d0));
                if (comp == 0) rx += rv; else ry += rv;
                // col terms: fixed column i, varying row
                float c0 = G(s, i, comp), c1 = G(s + 1, i, comp), c2 = G(s + 2, i, comp);
                float e0 = (c1 - c0) * (c1 - c0);
                float e1 = (c2 - c1) * (c2 - c1);
                float cv = fmaxf(0.08f, fabsf(e1 - e0));
                if (comp == 0) cx += cv; else cy += cv;
            }
        }
    }

    __shared__ float sh[4][64];
    sh[0][b] = rx; sh[1][b] = ry; sh[2][b] = cx; sh[3][b] = cy;
    __syncthreads();
    for (int off = 32; off > 0; off >>= 1) {
        if (b < off) {
            sh[0][b] += sh[0][b + off];
            sh[1][b] += sh[1][b + off];
            sh[2][b] += sh[2][b + off];
            sh[3][b] += sh[3][b + off];
        }
        __syncthreads();
    }

    if (b == 0) {
        float inv = 1.0f / 960.0f;   // 64 * 15 terms
        out[3200] = sh[0][0] * inv;
        out[3201] = sh[1][0] * inv;
        out[3202] = sh[2][0] * inv;
        out[3203] = sh[3][0] * inv;

        // curvature losses on grid[0] only
        const float* g0 = pts;  // batch 0
        #define G0(i, j, comp) g0[((i) * 5 + (j)) * 2 + (comp)]
        float rg = 0.f, cg = 0.f;
        for (int i = 0; i < 5; i++) {
            for (int s = 0; s < 3; s++) {
                {   // rows of g0: p along columns
                    float x0 = G0(i, s, 0),     y0 = G0(i, s, 1);
                    float x1 = G0(i, s + 1, 0), y1 = G0(i, s + 1, 1);
                    float x2 = G0(i, s + 2, 0), y2 = G0(i, s + 2, 1);
                    rg += fabsf((y1 - y0) * (x1 - x2) - (y1 - y2) * (x1 - x0));
                }
                {   // transposed: p along rows
                    float x0 = G0(s, i, 0),     y0 = G0(s, i, 1);
                    float x1 = G0(s + 1, i, 0), y1 = G0(s + 1, i, 1);
                    float x2 = G0(s + 2, i, 0), y2 = G0(s + 2, i, 1);
                    cg += fabsf((y1 - y0) * (x1 - x2) - (y1 - y2) * (x1 - x0));
                }
            }
        }
        out[3204] = fmaxf(rg, 0.02f);
        out[3205] = fmaxf(cg, 0.02f);
    }
}

// ---------------------------------------------------------------------------
// Host-side orchestration
// ---------------------------------------------------------------------------
static inline int cdiv(int a, int b) { return (a + b - 1) / b; }

extern "C" void kernel_launch(void* const* d_in, const int* in_sizes, int n_in,
                              void* d_out, int out_size)
{
    (void)in_sizes; (void)n_in; (void)out_size;

    const float* x = (const float*)d_in[0];
    const float* W[8];
    const float* Bi[8];
    for (int i = 0; i < 8; i++) {
        W[i]  = (const float*)d_in[1 + 2 * i];
        Bi[i] = (const float*)d_in[2 + 2 * i];
    }
    const float* fc1_w = (const float*)d_in[17];
    const float* fc1_b = (const float*)d_in[18];
    const float* fc2_w = (const float*)d_in[19];
    const float* fc2_b = (const float*)d_in[20];
    float* out = (float*)d_out;

    float* bufA; cudaGetSymbolAddress((void**)&bufA, g_bufA);
    float* bufB; cudaGetSymbolAddress((void**)&bufB, g_bufB);

    const int B = 64;
    // layer dims: {Cin, Hin, Win, Cout, Hout, Wout}
    const int L[8][6] = {
        {  5, 256, 192,   8, 128, 96},
        {  8, 128,  96,  16,  64, 48},
        { 16,  64,  48,  32,  32, 24},
        { 32,  32,  24,  64,  16, 12},
        { 64,  16,  12, 128,   8,  6},
        {128,   8,   6, 256,   4,  3},
        {256,   4,   3, 256,   4,  3},
        {256,   4,   3, 256,   4,  3},
    };

    const int TB = 256;

    // ---- Layer 0: inorm(relu(conv)) : x -> bufA
    {
        int tot = B * L[0][3] * L[0][4] * L[0][5];
        conv_kernel<4, 2, true><<<cdiv(tot, TB), TB>>>(
            x, W[0], Bi[0], bufA, B, L[0][0], L[0][1], L[0][2], L[0][3], L[0][4], L[0][5]);
        inorm_kernel<false><<<B * L[0][3], TB>>>(bufA, L[0][4] * L[0][5]);
    }

    // ---- Layers 1..5: relu(inorm(conv)), K=4 S=2, ping-pong A<->B
    float* src = bufA;
    float* dst = bufB;
    for (int l = 1; l <= 5; l++) {
        int tot = B * L[l][3] * L[l][4] * L[l][5];
        conv_kernel<4, 2, false><<<cdiv(tot, TB), TB>>>(
            src, W[l], Bi[l], dst, B, L[l][0], L[l][1], L[l][2], L[l][3], L[l][4], L[l][5]);
        inorm_kernel<true><<<B * L[l][3], TB>>>(dst, L[l][4] * L[l][5]);
        float* tmp = src; src = dst; dst = tmp;
    }

    // ---- Layers 6..7: relu(inorm(conv)), K=3 S=1
    for (int l = 6; l <= 7; l++) {
        int tot = B * L[l][3] * L[l][4] * L[l][5];
        conv_kernel<3, 1, false><<<cdiv(tot, TB), TB>>>(
            src, W[l], Bi[l], dst, B, L[l][0], L[l][1], L[l][2], L[l][3], L[l][4], L[l][5]);
        inorm_kernel<true><<<B * L[l][3], TB>>>(dst, L[l][4] * L[l][5]);
        float* tmp = src; src = dst; dst = tmp;
    }
    // after loop: src holds conv7 activations (64,256,4,3)

    // ---- Maxpool + flatten: src -> dst (64,512)
    maxpool_kernel<<<cdiv(64 * 256 * 2, TB), TB>>>(src, dst);

    // ---- FC1: dst (64,512) -> src (64,128)
    fc1_kernel<<<64, 128>>>(dst, fc1_w, fc1_b, src);

    // ---- FC2 + tanh: src (64,128) -> out[0..3199]
    fc2_kernel<<<64, 64>>>(src, fc2_w, fc2_b, out);

    // ---- Losses: out[3200..3205]
    loss_kernel<<<1, 64>>>(out);
}

// round 2
// speedup vs baseline: 2.7834x; 2.7834x over previous
#include <cuda_runtime.h>
#include <math.h>

// ---------------------------------------------------------------------------
// Scratch buffers (device globals -- no allocation inside kernel_launch)
// ---------------------------------------------------------------------------
#define MAX_A 6400000
#define MAX_B 3300000
__device__ float g_bufA[MAX_A];
__device__ float g_bufB[MAX_B];

// ---------------------------------------------------------------------------
// Tiled implicit-GEMM convolution.
// Each thread computes a CO_M x PIX_M (4x4) micro-tile of outputs.
// Weights for (CO_T x CI_T x K*K) staged in padded shared memory.
// Pixels indexed over flattened n = b*Hout*Wout + ho*Wout + wo (interleaved
// assignment so consecutive lanes touch consecutive pixels -> coalesced LDG).
// Optional Cin-split across blockIdx.z with atomicAdd partials (bias omitted:
// instance norm directly after conv is invariant to per-plane constants).
// ---------------------------------------------------------------------------
template<int K, int S, int CO_T, int CI_T, bool ATOMIC, bool BIAS, bool RELU>
__global__ void __launch_bounds__(256)
conv_tiled(const float* __restrict__ in,
           const float* __restrict__ w,
           const float* __restrict__ bias,
           float* __restrict__ out,
           int Cin, int Hin, int Win,
           int Cout, int Hout, int Wout,
           int NT, int CI_SPAN)
{
    constexpr int CO_M = 4, PIX_M = 4;
    constexpr int G    = CO_T / CO_M;     // co thread-groups
    constexpr int PTH  = 256 / G;         // pixel threads
    constexpr int PIXB = PTH * PIX_M;     // pixels per block
    constexpr int KK   = K * K;
    constexpr int WPITCH = CI_T * KK + 1; // pad to kill bank conflicts

    __shared__ float sw[CO_T * WPITCH];

    const int tco  = threadIdx.x % G;
    const int tpix = threadIdx.x / G;
    const int co0  = blockIdx.y * CO_T;
    const int nbase = blockIdx.x * PIXB;
    const int ci_begin = blockIdx.z * CI_SPAN;
    const int ci_end   = min(Cin, ci_begin + CI_SPAN);

    const int HW = Hout * Wout;
    const long HinWin = (long)Hin * Win;

    // Per-pixel setup
    int nidx[PIX_M];
    const float* pbase[PIX_M];   // input + b*Cin*Hin*Win + hbase*Win + wbase
    unsigned hmask[PIX_M], wmask[PIX_M];
    #pragma unroll
    for (int p = 0; p < PIX_M; p++) {
        int n = nbase + p * PTH + tpix;
        nidx[p] = n;
        bool val = (n < NT);
        int nn = val ? n : 0;
        int b  = nn / HW;
        int hw = nn % HW;
        int ho = hw / Wout, wo = hw % Wout;
        int hb = ho * S - 1, wb = wo * S - 1;
        unsigned hm = 0, wm = 0;
        #pragma unroll
        for (int k = 0; k < K; k++) {
            if (hb + k >= 0 && hb + k < Hin) hm |= 1u << k;
            if (wb + k >= 0 && wb + k < Win) wm |= 1u << k;
        }
        hmask[p] = val ? hm : 0u;
        wmask[p] = val ? wm : 0u;
        pbase[p] = in + (long)b * Cin * HinWin + (long)hb * Win + wb;
    }

    float acc[CO_M][PIX_M];
    #pragma unroll
    for (int m = 0; m < CO_M; m++)
        #pragma unroll
        for (int p = 0; p < PIX_M; p++) acc[m][p] = 0.f;

    for (int ci0 = ci_begin; ci0 < ci_end; ci0 += CI_T) {
        const int cicnt = min(CI_T, ci_end - ci0);
        __syncthreads();
        const int tot = CO_T * cicnt * KK;
        for (int idx = threadIdx.x; idx < tot; idx += 256) {
            int c = idx / (cicnt * KK);
            int r = idx % (cicnt * KK);
            sw[c * WPITCH + r] = w[((long)(co0 + c) * Cin + ci0) * KK + r];
        }
        __syncthreads();

        for (int ci = 0; ci < cicnt; ci++) {
            const float* wrow = &sw[(tco * CO_M) * WPITCH + ci * KK];
            const float* pci[PIX_M];
            #pragma unroll
            for (int p = 0; p < PIX_M; p++)
                pci[p] = pbase[p] + (long)(ci0 + ci) * HinWin;

            #pragma unroll
            for (int kh = 0; kh < K; kh++) {
                #pragma unroll
                for (int kw = 0; kw < K; kw++) {
                    float wv[CO_M];
                    #pragma unroll
                    for (int m = 0; m < CO_M; m++)
                        wv[m] = wrow[m * WPITCH + kh * K + kw];
                    float iv[PIX_M];
                    #pragma unroll
                    for (int p = 0; p < PIX_M; p++) {
                        bool ok = ((hmask[p] >> kh) & 1u) && ((wmask[p] >> kw) & 1u);
                        iv[p] = ok ? __ldg(pci[p] + kh * Win + kw) : 0.f;
                    }
                    #pragma unroll
                    for (int m = 0; m < CO_M; m++)
                        #pragma unroll
                        for (int p = 0; p < PIX_M; p++)
                            acc[m][p] = fmaf(wv[m], iv[p], acc[m][p]);
                }
            }
        }
    }

    // Epilogue
    #pragma unroll
    for (int p = 0; p < PIX_M; p++) {
        int n = nidx[p];
        if (n >= NT) continue;
        int b = n / HW, hw = n % HW;
        #pragma unroll
        for (int m = 0; m < CO_M; m++) {
            int co = co0 + tco * CO_M + m;
            long oidx = ((long)b * Cout + co) * HW + hw;
            if (ATOMIC) {
                atomicAdd(out + oidx, acc[m][p]);
            } else {
                float v = acc[m][p] + (BIAS ? bias[co] : 0.f);
                if (RELU) v = fmaxf(v, 0.f);
                out[oidx] = v;
            }
        }
    }
}

// ---------------------------------------------------------------------------
// Instance norm (in-place), one block per (b,c) plane. Optional trailing ReLU.
// blockDim must be a power of two.
// ---------------------------------------------------------------------------
template<bool RELU>
__global__ void inorm_kernel(float* __restrict__ data, int HW)
{
    float* p = data + (size_t)blockIdx.x * HW;
    float s = 0.f, ss = 0.f;
    for (int i = threadIdx.x; i < HW; i += blockDim.x) {
        float v = p[i];
        s  += v;
        ss += v * v;
    }
    __shared__ float sh_s[256];
    __shared__ float sh_ss[256];
    sh_s[threadIdx.x]  = s;
    sh_ss[threadIdx.x] = ss;
    __syncthreads();
    for (int off = blockDim.x >> 1; off > 0; off >>= 1) {
        if (threadIdx.x < off) {
            sh_s[threadIdx.x]  += sh_s[threadIdx.x + off];
            sh_ss[threadIdx.x] += sh_ss[threadIdx.x + off];
        }
        __syncthreads();
    }
    float invN = 1.0f / (float)HW;
    float m    = sh_s[0] * invN;
    float var  = sh_ss[0] * invN - m * m;
    float r    = rsqrtf(var + 1e-5f);
    for (int i = threadIdx.x; i < HW; i += blockDim.x) {
        float v = (p[i] - m) * r;
        if (RELU) v = fmaxf(v, 0.0f);
        p[i] = v;
    }
}

// ---------------------------------------------------------------------------
// Instance norm for tiny planes (HW <= 32): one warp per plane, 8 planes/block.
// ---------------------------------------------------------------------------
template<bool RELU>
__global__ void inorm_small_kernel(float* __restrict__ data, int HW, int NPLANE)
{
    int warp = (blockIdx.x * blockDim.x + threadIdx.x) >> 5;
    int lane = threadIdx.x & 31;
    if (warp >= NPLANE) return;
    float* p = data + (size_t)warp * HW;
    float v = (lane < HW) ? p[lane] : 0.f;
    float s = v, ss = v * v;
    #pragma unroll
    for (int off = 16; off > 0; off >>= 1) {
        s  += __shfl_xor_sync(0xFFFFFFFFu, s,  off);
        ss += __shfl_xor_sync(0xFFFFFFFFu, ss, off);
    }
    float invN = 1.0f / (float)HW;
    float m    = s * invN;
    float var  = ss * invN - m * m;
    float r    = rsqrtf(var + 1e-5f);
    if (lane < HW) {
        float o = (v - m) * r;
        if (RELU) o = fmaxf(o, 0.0f);
        p[lane] = o;
    }
}

// ---------------------------------------------------------------------------
// Maxpool 2x2 stride 2 VALID on (64,256,4,3) -> flatten to (64,512)
// ---------------------------------------------------------------------------
__global__ void maxpool_kernel(const float* __restrict__ in, float* __restrict__ out)
{
    int idx = blockIdx.x * blockDim.x + threadIdx.x;
    if (idx >= 64 * 256 * 2) return;
    int i = idx % 2;
    int c = (idx / 2) % 256;
    int b = idx / 512;
    const float* p = in + (((size_t)b * 256 + c) * 4 + 2 * i) * 3;
    float v = fmaxf(fmaxf(p[0], p[1]), fmaxf(p[3], p[4]));
    out[(size_t)b * 512 + c * 2 + i] = v;
}

// ---------------------------------------------------------------------------
// FC1: (64,512) @ (128,512)^T + b, ReLU.
// ---------------------------------------------------------------------------
__global__ void fc1_kernel(const float* __restrict__ in,
                           const float* __restrict__ w,
                           const float* __restrict__ bias,
                           float* __restrict__ out)
{
    int b = blockIdx.x;
    int j = threadIdx.x;           // 128 threads
    __shared__ float xs[512];
    for (int k = threadIdx.x; k < 512; k += 128) xs[k] = in[(size_t)b * 512 + k];
    __syncthreads();
    const float* wr = w + (size_t)j * 512;
    float acc = bias[j];
    #pragma unroll 8
    for (int k = 0; k < 512; k++)
        acc = fmaf(xs[k], __ldg(wr + k), acc);
    out[(size_t)b * 128 + j] = fmaxf(acc, 0.0f);
}

// ---------------------------------------------------------------------------
// FC2: (64,128) @ (50,128)^T + b, tanh. Writes coor directly into d_out.
// ---------------------------------------------------------------------------
__global__ void fc2_kernel(const float* __restrict__ in,
                           const float* __restrict__ w,
                           const float* __restrict__ bias,
                           float* __restrict__ out)
{
    int b = blockIdx.x;
    int j = threadIdx.x;           // 64 threads, guard at 50
    if (j >= 50) return;
    const float* x  = in + (size_t)b * 128;
    const float* wr = w  + (size_t)j * 128;
    float acc = bias[j];
    #pragma unroll 8
    for (int k = 0; k < 128; k++)
        acc = fmaf(__ldg(x + k), __ldg(wr + k), acc);
    out[(size_t)b * 50 + j] = tanhf(acc);
}

// ---------------------------------------------------------------------------
// Loss kernel. Single block, 64 threads (thread = batch).
// ---------------------------------------------------------------------------
__global__ void loss_kernel(float* __restrict__ out)
{
    const float* pts = out;
    int b = threadIdx.x;
    const float* g = pts + (size_t)b * 50;
    #define G(i, j, comp) g[((i) * 5 + (j)) * 2 + (comp)]

    float rx = 0.f, ry = 0.f, cx = 0.f, cy = 0.f;
    for (int i = 0; i < 5; i++) {
        for (int s = 0; s < 3; s++) {
            #pragma unroll
            for (int comp = 0; comp < 2; comp++) {
                float a0 = G(i, s, comp), a1 = G(i, s + 1, comp), a2 = G(i, s + 2, comp);
                float d0 = (a1 - a0) * (a1 - a0);
                float d1 = (a2 - a1) * (a2 - a1);
                float rv = fmaxf(0.08f, fabsf(d1 - d0));
                if (comp == 0) rx += rv; else ry += rv;
                float c0 = G(s, i, comp), c1 = G(s + 1, i, comp), c2 = G(s + 2, i, comp);
                float e0 = (c1 - c0) * (c1 - c0);
                float e1 = (c2 - c1) * (c2 - c1);
                float cv = fmaxf(0.08f, fabsf(e1 - e0));
                if (comp == 0) cx += cv; else cy += cv;
            }
        }
    }

    __shared__ float sh[4][64];
    sh[0][b] = rx; sh[1][b] = ry; sh[2][b] = cx; sh[3][b] = cy;
    __syncthreads();
    for (int off = 32; off > 0; off >>= 1) {
        if (b < off) {
            sh[0][b] += sh[0][b + off];
            sh[1][b] += sh[1][b + off];
            sh[2][b] += sh[2][b + off];
            sh[3][b] += sh[3][b + off];
        }
        __syncthreads();
    }

    if (b == 0) {
        float inv = 1.0f / 960.0f;
        out[3200] = sh[0][0] * inv;
        out[3201] = sh[1][0] * inv;
        out[3202] = sh[2][0] * inv;
        out[3203] = sh[3][0] * inv;

        const float* g0 = pts;
        #define G0(i, j, comp) g0[((i) * 5 + (j)) * 2 + (comp)]
        float rg = 0.f, cg = 0.f;
        for (int i = 0; i < 5; i++) {
            for (int s = 0; s < 3; s++) {
                {
                    float x0 = G0(i, s, 0),     y0 = G0(i, s, 1);
                    float x1 = G0(i, s + 1, 0), y1 = G0(i, s + 1, 1);
                    float x2 = G0(i, s + 2, 0), y2 = G0(i, s + 2, 1);
                    rg += fabsf((y1 - y0) * (x1 - x2) - (y1 - y2) * (x1 - x0));
                }
                {
                    float x0 = G0(s, i, 0),     y0 = G0(s, i, 1);
                    float x1 = G0(s + 1, i, 0), y1 = G0(s + 1, i, 1);
                    float x2 = G0(s + 2, i, 0), y2 = G0(s + 2, i, 1);
                    cg += fabsf((y1 - y0) * (x1 - x2) - (y1 - y2) * (x1 - x0));
                }
            }
        }
        out[3204] = fmaxf(rg, 0.02f);
        out[3205] = fmaxf(cg, 0.02f);
    }
}

// ---------------------------------------------------------------------------
// Host-side orchestration
// ---------------------------------------------------------------------------
static inline int cdiv(int a, int b) { return (a + b - 1) / b; }

extern "C" void kernel_launch(void* const* d_in, const int* in_sizes, int n_in,
                              void* d_out, int out_size)
{
    (void)in_sizes; (void)n_in; (void)out_size;

    const float* x = (const float*)d_in[0];
    const float* W[8];
    const float* Bi[8];
    for (int i = 0; i < 8; i++) {
        W[i]  = (const float*)d_in[1 + 2 * i];
        Bi[i] = (const float*)d_in[2 + 2 * i];
    }
    const float* fc1_w = (const float*)d_in[17];
    const float* fc1_b = (const float*)d_in[18];
    const float* fc2_w = (const float*)d_in[19];
    const float* fc2_b = (const float*)d_in[20];
    float* out = (float*)d_out;

    float* bufA; cudaGetSymbolAddress((void**)&bufA, g_bufA);
    float* bufB; cudaGetSymbolAddress((void**)&bufB, g_bufB);

    const int B = 64;
    // {Cin, Hin, Win, Cout, Hout, Wout}
    const int L[8][6] = {
        {  5, 256, 192,   8, 128, 96},
        {  8, 128,  96,  16,  64, 48},
        { 16,  64,  48,  32,  32, 24},
        { 32,  32,  24,  64,  16, 12},
        { 64,  16,  12, 128,   8,  6},
        {128,   8,   6, 256,   4,  3},
        {256,   4,   3, 256,   4,  3},
        {256,   4,   3, 256,   4,  3},
    };

    // ---- Layer 0: relu(conv) -> inorm : x -> bufA   (bias kept: relu precedes inorm)
    {
        int NT = B * L[0][4] * L[0][5];                  // 786432
        dim3 grid(cdiv(NT, 512), 1, 1);
        conv_tiled<4, 2, 8, 5, false, true, true><<<grid, 256>>>(
            x, W[0], Bi[0], bufA,
            L[0][0], L[0][1], L[0][2], L[0][3], L[0][4], L[0][5], NT, 5);
        inorm_kernel<false><<<B * L[0][3], 256>>>(bufA, L[0][4] * L[0][5]);
    }

    // ---- Layer 1: bufA -> bufB  (bias dropped: inorm-invariant)
    {
        int NT = B * L[1][4] * L[1][5];                  // 196608
        dim3 grid(cdiv(NT, 256), 1, 1);
        conv_tiled<4, 2, 16, 8, false, false, false><<<grid, 256>>>(
            bufA, W[1], nullptr, bufB,
            L[1][0], L[1][1], L[1][2], L[1][3], L[1][4], L[1][5], NT, 8);
        inorm_kernel<true><<<B * L[1][3], 256>>>(bufB, L[1][4] * L[1][5]);
    }

    // ---- Layer 2: bufB -> bufA
    {
        int NT = B * L[2][4] * L[2][5];                  // 49152
        dim3 grid(cdiv(NT, 128), 1, 1);
        conv_tiled<4, 2, 32, 16, false, false, false><<<grid, 256>>>(
            bufB, W[2], nullptr, bufA,
            L[2][0], L[2][1], L[2][2], L[2][3], L[2][4], L[2][5], NT, 16);
        inorm_kernel<true><<<B * L[2][3], 128>>>(bufA, L[2][4] * L[2][5]);
    }

    // ---- Layer 3: bufA -> bufB  (Cin split x2, atomic)
    {
        int NT = B * L[3][4] * L[3][5];                  // 12288
        size_t outN = (size_t)B * L[3][3] * L[3][4] * L[3][5];
        cudaMemsetAsync(bufB, 0, outN * sizeof(float));
        dim3 grid(cdiv(NT, 128), L[3][3] / 32, 2);       // (96, 2, 2)
        conv_tiled<4, 2, 32, 16, true, false, false><<<grid, 256>>>(
            bufA, W[3], nullptr, bufB,
            L[3][0], L[3][1], L[3][2], L[3][3], L[3][4], L[3][5], NT, 16);
        inorm_kernel<true><<<B * L[3][3], 64>>>(bufB, L[3][4] * L[3][5]);
    }

    // ---- Layer 4: bufB -> bufA  (Cin split x4, atomic)
    {
        int NT = B * L[4][4] * L[4][5];                  // 3072
        size_t outN = (size_t)B * L[4][3] * L[4][4] * L[4][5];
        cudaMemsetAsync(bufA, 0, outN * sizeof(float));
        dim3 grid(cdiv(NT, 128), L[4][3] / 32, 4);       // (24, 4, 4)
        conv_tiled<4, 2, 32, 16, true, false, false><<<grid, 256>>>(
            bufB, W[4], nullptr, bufA,
            L[4][0], L[4][1], L[4][2], L[4][3], L[4][4], L[4][5], NT, 16);
        inorm_kernel<true><<<B * L[4][3], 64>>>(bufA, L[4][4] * L[4][5]);
    }

    // ---- Layer 5: bufA -> bufB  (Cin split x8, atomic)
    {
        int NT = B * L[5][4] * L[5][5];                  // 768
        size_t outN = (size_t)B * L[5][3] * L[5][4] * L[5][5];
        cudaMemsetAsync(bufB, 0, outN * sizeof(float));
        dim3 grid(cdiv(NT, 128), L[5][3] / 32, 8);       // (6, 8, 8)
        conv_tiled<4, 2, 32, 16, true, false, false><<<grid, 256>>>(
            bufA, W[5], nullptr, bufB,
            L[5][0], L[5][1], L[5][2], L[5][3], L[5][4], L[5][5], NT, 16);
        int nplanes = B * L[5][3];
        inorm_small_kernel<true><<<cdiv(nplanes * 32, 256), 256>>>(bufB, 12, nplanes);
    }

    // ---- Layers 6,7: K=3 S=1  (Cin split x8, atomic)
    float* src = bufB;
    float* dst = bufA;
    for (int l = 6; l <= 7; l++) {
        int NT = B * L[l][4] * L[l][5];                  // 768
        size_t outN = (size_t)B * L[l][3] * L[l][4] * L[l][5];
        cudaMemsetAsync(dst, 0, outN * sizeof(float));
        dim3 grid(cdiv(NT, 128), L[l][3] / 32, 8);       // (6, 8, 8)
        conv_tiled<3, 1, 32, 32, true, false, false><<<grid, 256>>>(
            src, W[l], nullptr, dst,
            L[l][0], L[l][1], L[l][2], L[l][3], L[l][4], L[l][5], NT, 32);
        int nplanes = B * L[l][3];
        inorm_small_kernel<true><<<cdiv(nplanes * 32, 256), 256>>>(dst, 12, nplanes);
        float* tmp = src; src = dst; dst = tmp;
    }
    // after loop: src = bufB holds conv7 activations (64,256,4,3)

    // ---- Maxpool + flatten: src -> dst (64,512)
    maxpool_kernel<<<cdiv(64 * 256 * 2, 256), 256>>>(src, dst);

    // ---- FC1: dst (64,512) -> src (64,128)
    fc1_kernel<<<64, 128>>>(dst, fc1_w, fc1_b, src);

    // ---- FC2 + tanh: src (64,128) -> out[0..3199]
    fc2_kernel<<<64, 64>>>(src, fc2_w, fc2_b, out);

    // ---- Losses: out[3200..3205]
    loss_kernel<<<1, 64>>>(out);
}

// round 3
// speedup vs baseline: 3.4990x; 1.2571x over previous
#include <cuda_runtime.h>
#include <math.h>

// ---------------------------------------------------------------------------
// Scratch buffers (device globals -- no allocation inside kernel_launch)
// ---------------------------------------------------------------------------
__device__ float g_bufX[16100000];   // padded network input 64*5*258*194
__device__ float g_bufA[6400000];    // unpadded conv outputs (max 6.29M)
__device__ float g_bufB[6600000];    // padded activations (max 6.52M)
__device__ float g_bufC[6600000];    // padded activations

// ---------------------------------------------------------------------------
// Zero-pad copy: src (H x W planes, contiguous) -> dst ((H+2) x (W+2), halo=0)
// One block per plane.
// ---------------------------------------------------------------------------
__global__ void pad_copy_kernel(const float* __restrict__ src, float* __restrict__ dst,
                                int H, int W, int HP, int WP)
{
    const float* s = src + (size_t)blockIdx.x * H * W;
    float* d = dst + (size_t)blockIdx.x * HP * WP;
    int tot = HP * WP;
    for (int i = threadIdx.x; i < tot; i += blockDim.x) {
        int h = i / WP, w = i % WP;
        bool in = (h >= 1) && (h <= H) && (w >= 1) && (w <= W);
        d[i] = in ? s[(h - 1) * W + (w - 1)] : 0.f;
    }
}

// ---------------------------------------------------------------------------
// Tiled implicit-GEMM convolution on PADDED input. No bounds checks.
// All geometry compile-time. Thread computes CO_M x PIX_M (4x4) outputs.
// ---------------------------------------------------------------------------
template<int K, int S, int CIN, int HP, int WP, int COUT, int HOUT, int WOUT,
         int CO_T, int CI_T, int ZSPLIT, bool ATOMIC, bool BIAS, bool RELU>
__global__ void __launch_bounds__(256)
conv_tiled(const float* __restrict__ in,
           const float* __restrict__ w,
           const float* __restrict__ bias,
           float* __restrict__ out)
{
    constexpr int CO_M = 4, PIX_M = 4;
    constexpr int G    = CO_T / CO_M;
    constexpr int PTH  = 256 / G;
    constexpr int PIXB = PTH * PIX_M;
    constexpr int KK   = K * K;
    constexpr int WPITCH = CI_T * KK + 1;
    constexpr int HW   = HOUT * WOUT;
    constexpr int NT   = 64 * HW;
    constexpr int PSZ  = HP * WP;
    constexpr int CI_SPAN = CIN / ZSPLIT;
    static_assert(CI_SPAN == CI_T, "one smem weight tile per block");

    __shared__ float sw[CO_T * WPITCH];

    const int tco  = threadIdx.x % G;
    const int tpix = threadIdx.x / G;
    const int co0  = blockIdx.y * CO_T;
    const int nbase = blockIdx.x * PIXB;
    const int ci_begin = blockIdx.z * CI_SPAN;

    // stage weights: contiguous CI_T*KK per output channel
    {
        const int tot = CO_T * CI_T * KK;
        const float* wsrc = w + ((long)co0 * CIN + ci_begin) * KK;
        for (int idx = threadIdx.x; idx < tot; idx += 256) {
            int c = idx / (CI_T * KK);
            int r = idx % (CI_T * KK);
            sw[c * WPITCH + r] = wsrc[(long)c * CIN * KK + r];
        }
    }
    __syncthreads();

    // per-pixel input base pointers (padded layout; no masks needed)
    int nidx[PIX_M];
    const float* pci[PIX_M];
    #pragma unroll
    for (int p = 0; p < PIX_M; p++) {
        int n = nbase + p * PTH + tpix;
        nidx[p] = n;
        int nn = (n < NT) ? n : 0;
        int b  = nn / HW;
        int hw = nn % HW;
        int ho = hw / WOUT, wo = hw % WOUT;
        pci[p] = in + ((long)b * CIN + ci_begin) * PSZ + (ho * S) * WP + (wo * S);
    }

    float acc[CO_M][PIX_M];
    #pragma unroll
    for (int m = 0; m < CO_M; m++)
        #pragma unroll
        for (int p = 0; p < PIX_M; p++) acc[m][p] = 0.f;

    const float* wrow0 = &sw[(tco * CO_M) * WPITCH];
    for (int ci = 0; ci < CI_T; ci++) {
        const float* wrow = wrow0 + ci * KK;
        #pragma unroll
        for (int kh = 0; kh < K; kh++) {
            #pragma unroll
            for (int kw = 0; kw < K; kw++) {
                float wv[CO_M];
                #pragma unroll
                for (int m = 0; m < CO_M; m++)
                    wv[m] = wrow[m * WPITCH + kh * K + kw];
                float iv[PIX_M];
                #pragma unroll
                for (int p = 0; p < PIX_M; p++)
                    iv[p] = __ldg(pci[p] + kh * WP + kw);
                #pragma unroll
                for (int m = 0; m < CO_M; m++)
                    #pragma unroll
                    for (int p = 0; p < PIX_M; p++)
                        acc[m][p] = fmaf(wv[m], iv[p], acc[m][p]);
            }
        }
        #pragma unroll
        for (int p = 0; p < PIX_M; p++) pci[p] += PSZ;
    }

    // epilogue (unpadded output layout)
    #pragma unroll
    for (int p = 0; p < PIX_M; p++) {
        int n = nidx[p];
        if (n >= NT) continue;
        int b = n / HW, hw = n % HW;
        #pragma unroll
        for (int m = 0; m < CO_M; m++) {
            int co = co0 + tco * CO_M + m;
            long oidx = ((long)b * COUT + co) * HW + hw;
            if (ATOMIC) {
                atomicAdd(out + oidx, acc[m][p]);
            } else {
                float v = acc[m][p] + (BIAS ? bias[co] : 0.f);
                if (RELU) v = fmaxf(v, 0.f);
                out[oidx] = v;
            }
        }
    }
}

// ---------------------------------------------------------------------------
// Instance norm reading unpadded conv output, writing PADDED layout (halo=0).
// One block per (b,c) plane. blockDim power of two (<=256).
// ---------------------------------------------------------------------------
template<bool RELU>
__global__ void inorm_pad_kernel(const float* __restrict__ src, float* __restrict__ dst,
                                 int H, int W, int HP, int WP)
{
    const int HW = H * W;
    const float* s = src + (size_t)blockIdx.x * HW;
    float* d = dst + (size_t)blockIdx.x * HP * WP;

    float sum = 0.f, ssq = 0.f;
    for (int i = threadIdx.x; i < HW; i += blockDim.x) {
        float v = s[i];
        sum += v; ssq += v * v;
    }
    __shared__ float sh_s[256];
    __shared__ float sh_q[256];
    sh_s[threadIdx.x] = sum;
    sh_q[threadIdx.x] = ssq;
    __syncthreads();
    for (int off = blockDim.x >> 1; off > 0; off >>= 1) {
        if (threadIdx.x < off) {
            sh_s[threadIdx.x] += sh_s[threadIdx.x + off];
            sh_q[threadIdx.x] += sh_q[threadIdx.x + off];
        }
        __syncthreads();
    }
    float invN = 1.0f / (float)HW;
    float m = sh_s[0] * invN;
    float var = sh_q[0] * invN - m * m;
    float r = rsqrtf(var + 1e-5f);

    int tot = HP * WP;
    for (int i = threadIdx.x; i < tot; i += blockDim.x) {
        int h = i / WP, w = i % WP;
        bool in = (h >= 1) && (h <= H) && (w >= 1) && (w <= W);
        float v = 0.f;
        if (in) {
            v = (s[(h - 1) * W + (w - 1)] - m) * r;
            if (RELU) v = fmaxf(v, 0.f);
        }
        d[i] = v;
    }
}

// ---------------------------------------------------------------------------
// Tiny-plane instance norm + pad: src 4x3 planes -> dst 6x5 padded. Warp/plane.
// ---------------------------------------------------------------------------
template<bool RELU>
__global__ void inorm_small_pad_kernel(const float* __restrict__ src,
                                       float* __restrict__ dst, int NPLANE)
{
    int warp = (blockIdx.x * blockDim.x + threadIdx.x) >> 5;
    int lane = threadIdx.x & 31;
    if (warp >= NPLANE) return;
    const float* s = src + (size_t)warp * 12;
    float* d = dst + (size_t)warp * 30;

    int h = lane / 5, w = lane % 5;
    bool interior = (lane < 30) && (h >= 1) && (h <= 4) && (w >= 1) && (w <= 3);
    float v = interior ? s[(h - 1) * 3 + (w - 1)] : 0.f;
    float sum = v, ssq = v * v;
    #pragma unroll
    for (int off = 16; off > 0; off >>= 1) {
        sum += __shfl_xor_sync(0xFFFFFFFFu, sum, off);
        ssq += __shfl_xor_sync(0xFFFFFFFFu, ssq, off);
    }
    float invN = 1.0f / 12.0f;
    float m = sum * invN;
    float var = ssq * invN - m * m;
    float r = rsqrtf(var + 1e-5f);
    if (lane < 30) {
        float o = 0.f;
        if (interior) {
            o = (v - m) * r;
            if (RELU) o = fmaxf(o, 0.f);
        }
        d[lane] = o;
    }
}

// ---------------------------------------------------------------------------
// Maxpool on PADDED (6x5) planes of conv7 output -> flatten (64,512)
// ---------------------------------------------------------------------------
__global__ void maxpool_kernel(const float* __restrict__ in, float* __restrict__ out)
{
    int idx = blockIdx.x * blockDim.x + threadIdx.x;
    if (idx >= 64 * 256 * 2) return;
    int i = idx % 2;
    int c = (idx / 2) % 256;
    int b = idx / 512;
    const float* p = in + ((size_t)b * 256 + c) * 30;
    int r0 = (2 * i + 1) * 5 + 1;
    int r1 = (2 * i + 2) * 5 + 1;
    float v = fmaxf(fmaxf(p[r0], p[r0 + 1]), fmaxf(p[r1], p[r1 + 1]));
    out[(size_t)b * 512 + c * 2 + i] = v;
}

// ---------------------------------------------------------------------------
// FC1: (64,512) @ (128,512)^T + b, ReLU.
// ---------------------------------------------------------------------------
__global__ void fc1_kernel(const float* __restrict__ in,
                           const float* __restrict__ w,
                           const float* __restrict__ bias,
                           float* __restrict__ out)
{
    int b = blockIdx.x;
    int j = threadIdx.x;
    __shared__ float xs[512];
    for (int k = threadIdx.x; k < 512; k += 128) xs[k] = in[(size_t)b * 512 + k];
    __syncthreads();
    const float* wr = w + (size_t)j * 512;
    float acc = bias[j];
    #pragma unroll 8
    for (int k = 0; k < 512; k++)
        acc = fmaf(xs[k], __ldg(wr + k), acc);
    out[(size_t)b * 128 + j] = fmaxf(acc, 0.0f);
}

// ---------------------------------------------------------------------------
// FC2: (64,128) @ (50,128)^T + b, tanh -> d_out coor
// ---------------------------------------------------------------------------
__global__ void fc2_kernel(const float* __restrict__ in,
                           const float* __restrict__ w,
                           const float* __restrict__ bias,
                           float* __restrict__ out)
{
    int b = blockIdx.x;
    int j = threadIdx.x;
    if (j >= 50) return;
    const float* x  = in + (size_t)b * 128;
    const float* wr = w  + (size_t)j * 128;
    float acc = bias[j];
    #pragma unroll 8
    for (int k = 0; k < 128; k++)
        acc = fmaf(__ldg(x + k), __ldg(wr + k), acc);
    out[(size_t)b * 50 + j] = tanhf(acc);
}

// ---------------------------------------------------------------------------
// Loss kernel. Single block, 64 threads (thread = batch).
// ---------------------------------------------------------------------------
__global__ void loss_kernel(float* __restrict__ out)
{
    const float* pts = out;
    int b = threadIdx.x;
    const float* g = pts + (size_t)b * 50;
    #define G(i, j, comp) g[((i) * 5 + (j)) * 2 + (comp)]

    float rx = 0.f, ry = 0.f, cx = 0.f, cy = 0.f;
    for (int i = 0; i < 5; i++) {
        for (int s = 0; s < 3; s++) {
            #pragma unroll
            for (int comp = 0; comp < 2; comp++) {
                float a0 = G(i, s, comp), a1 = G(i, s + 1, comp), a2 = G(i, s + 2, comp);
                float d0 = (a1 - a0) * (a1 - a0);
                float d1 = (a2 - a1) * (a2 - a1);
                float rv = fmaxf(0.08f, fabsf(d1 - d0));
                if (comp == 0) rx += rv; else ry += rv;
                float c0 = G(s, i, comp), c1 = G(s + 1, i, comp), c2 = G(s + 2, i, comp);
                float e0 = (c1 - c0) * (c1 - c0);
                float e1 = (c2 - c1) * (c2 - c1);
                float cv = fmaxf(0.08f, fabsf(e1 - e0));
                if (comp == 0) cx += cv; else cy += cv;
            }
        }
    }

    __shared__ float sh[4][64];
    sh[0][b] = rx; sh[1][b] = ry; sh[2][b] = cx; sh[3][b] = cy;
    __syncthreads();
    for (int off = 32; off > 0; off >>= 1) {
        if (b < off) {
            sh[0][b] += sh[0][b + off];
            sh[1][b] += sh[1][b + off];
            sh[2][b] += sh[2][b + off];
            sh[3][b] += sh[3][b + off];
        }
        __syncthreads();
    }

    if (b == 0) {
        float inv = 1.0f / 960.0f;
        out[3200] = sh[0][0] * inv;
        out[3201] = sh[1][0] * inv;
        out[3202] = sh[2][0] * inv;
        out[3203] = sh[3][0] * inv;

        const float* g0 = pts;
        #define G0(i, j, comp) g0[((i) * 5 + (j)) * 2 + (comp)]
        float rg = 0.f, cg = 0.f;
        for (int i = 0; i < 5; i++) {
            for (int s = 0; s < 3; s++) {
                {
                    float x0 = G0(i, s, 0),     y0 = G0(i, s, 1);
                    float x1 = G0(i, s + 1, 0), y1 = G0(i, s + 1, 1);
                    float x2 = G0(i, s + 2, 0), y2 = G0(i, s + 2, 1);
                    rg += fabsf((y1 - y0) * (x1 - x2) - (y1 - y2) * (x1 - x0));
                }
                {
                    float x0 = G0(s, i, 0),     y0 = G0(s, i, 1);
                    float x1 = G0(s + 1, i, 0), y1 = G0(s + 1, i, 1);
                    float x2 = G0(s + 2, i, 0), y2 = G0(s + 2, i, 1);
                    cg += fabsf((y1 - y0) * (x1 - x2) - (y1 - y2) * (x1 - x0));
                }
            }
        }
        out[3204] = fmaxf(rg, 0.02f);
        out[3205] = fmaxf(cg, 0.02f);
    }
}

// ---------------------------------------------------------------------------
// Host-side orchestration
// ---------------------------------------------------------------------------
static inline int cdiv(int a, int b) { return (a + b - 1) / b; }

extern "C" void kernel_launch(void* const* d_in, const int* in_sizes, int n_in,
                              void* d_out, int out_size)
{
    (void)in_sizes; (void)n_in; (void)out_size;

    const float* x = (const float*)d_in[0];
    const float* W[8];
    const float* Bi[8];
    for (int i = 0; i < 8; i++) {
        W[i]  = (const float*)d_in[1 + 2 * i];
        Bi[i] = (const float*)d_in[2 + 2 * i];
    }
    const float* fc1_w = (const float*)d_in[17];
    const float* fc1_b = (const float*)d_in[18];
    const float* fc2_w = (const float*)d_in[19];
    const float* fc2_b = (const float*)d_in[20];
    float* out = (float*)d_out;

    float* X; cudaGetSymbolAddress((void**)&X, g_bufX);
    float* A; cudaGetSymbolAddress((void**)&A, g_bufA);
    float* Bb; cudaGetSymbolAddress((void**)&Bb, g_bufB);
    float* C; cudaGetSymbolAddress((void**)&C, g_bufC);

    // ---- pad network input: x (64,5,256,192) -> X (64,5,258,194)
    pad_copy_kernel<<<64 * 5, 256>>>(x, X, 256, 192, 258, 194);

    // ---- L0: conv(X)->A [relu+bias], inorm A->B (padded 130x98)
    {
        constexpr int NT = 64 * 128 * 96;
        dim3 grid(NT / 512, 1, 1);
        conv_tiled<4, 2, 5, 258, 194, 8, 128, 96, 8, 5, 1, false, true, true>
            <<<grid, 256>>>(X, W[0], Bi[0], A);
        inorm_pad_kernel<false><<<64 * 8, 256>>>(A, Bb, 128, 96, 130, 98);
    }
    // ---- L1: conv(B)->A, inorm A->C (padded 66x50)
    {
        constexpr int NT = 64 * 64 * 48;
        dim3 grid(NT / 256, 1, 1);
        conv_tiled<4, 2, 8, 130, 98, 16, 64, 48, 16, 8, 1, false, false, false>
            <<<grid, 256>>>(Bb, W[1], nullptr, A);
        inorm_pad_kernel<true><<<64 * 16, 256>>>(A, C, 64, 48, 66, 50);
    }
    // ---- L2: conv(C)->A, inorm A->B (padded 34x26)
    {
        constexpr int NT = 64 * 32 * 24;
        dim3 grid(NT / 128, 1, 1);
        conv_tiled<4, 2, 16, 66, 50, 32, 32, 24, 32, 16, 1, false, false, false>
            <<<grid, 256>>>(C, W[2], nullptr, A);
        inorm_pad_kernel<true><<<64 * 32, 256>>>(A, Bb, 32, 24, 34, 26);
    }
    // ---- L3: conv(B)->A (Z=2 atomic), inorm A->C (padded 18x14)
    {
        constexpr int NT = 64 * 16 * 12;
        cudaMemsetAsync(A, 0, (size_t)64 * 64 * 16 * 12 * sizeof(float));
        dim3 grid(NT / 128, 2, 2);
        conv_tiled<4, 2, 32, 34, 26, 64, 16, 12, 32, 16, 2, true, false, false>
            <<<grid, 256>>>(Bb, W[3], nullptr, A);
        inorm_pad_kernel<true><<<64 * 64, 64>>>(A, C, 16, 12, 18, 14);
    }
    // ---- L4: conv(C)->A (Z=4 atomic), inorm A->B (padded 10x8)
    {
        constexpr int NT = 64 * 8 * 6;
        cudaMemsetAsync(A, 0, (size_t)64 * 128 * 8 * 6 * sizeof(float));
        dim3 grid(NT / 128, 4, 4);
        conv_tiled<4, 2, 64, 18, 14, 128, 8, 6, 32, 16, 4, true, false, false>
            <<<grid, 256>>>(C, W[4], nullptr, A);
        inorm_pad_kernel<true><<<64 * 128, 64>>>(A, Bb, 8, 6, 10, 8);
    }
    // ---- L5: conv(B)->A (Z=8 atomic), inorm_small A->C (padded 6x5)
    {
        constexpr int NT = 64 * 4 * 3;
        cudaMemsetAsync(A, 0, (size_t)64 * 256 * 4 * 3 * sizeof(float));
        dim3 grid(NT / 128, 8, 8);
        conv_tiled<4, 2, 128, 10, 8, 256, 4, 3, 32, 16, 8, true, false, false>
            <<<grid, 256>>>(Bb, W[5], nullptr, A);
        int np = 64 * 256;
        inorm_small_pad_kernel<true><<<cdiv(np * 32, 256), 256>>>(A, C, np);
    }
    // ---- L6: conv(C)->A (Z=8 atomic), inorm_small A->B
    {
        constexpr int NT = 64 * 4 * 3;
        cudaMemsetAsync(A, 0, (size_t)64 * 256 * 4 * 3 * sizeof(float));
        dim3 grid(NT / 128, 8, 8);
        conv_tiled<3, 1, 256, 6, 5, 256, 4, 3, 32, 32, 8, true, false, false>
            <<<grid, 256>>>(C, W[6], nullptr, A);
        int np = 64 * 256;
        inorm_small_pad_kernel<true><<<cdiv(np * 32, 256), 256>>>(A, Bb, np);
    }
    // ---- L7: conv(B)->A (Z=8 atomic), inorm_small A->C
    {
        constexpr int NT = 64 * 4 * 3;
        cudaMemsetAsync(A, 0, (size_t)64 * 256 * 4 * 3 * sizeof(float));
        dim3 grid(NT / 128, 8, 8);
        conv_tiled<3, 1, 256, 6, 5, 256, 4, 3, 32, 32, 8, true, false, false>
            <<<grid, 256>>>(Bb, W[7], nullptr, A);
        int np = 64 * 256;
        inorm_small_pad_kernel<true><<<cdiv(np * 32, 256), 256>>>(A, C, np);
    }

    // ---- maxpool (padded C) -> B (64,512)
    maxpool_kernel<<<cdiv(64 * 256 * 2, 256), 256>>>(C, Bb);
    // ---- FC1: B -> A (64,128)
    fc1_kernel<<<64, 128>>>(Bb, fc1_w, fc1_b, A);
    // ---- FC2 + tanh: A -> out[0..3199]
    fc2_kernel<<<64, 64>>>(A, fc2_w, fc2_b, out);
    // ---- losses
    loss_kernel<<<1, 64>>>(out);
}